// round 13
// baseline (speedup 1.0000x reference)
#include <cuda_runtime.h>

#define BB 64
#define CC 512
#define HH 28
#define WW 28
#define HWSZ (HH*WW)
#define HID 32
#define NPLANE (BB*CC)
#define NLAYERS 4
#define QPP 196            // float4 quads per plane
#define PPB 8              // planes per block (1 warp each)
#define NUP (NPLANE/PPB)   // 4096 update blocks
#define NSLOT 49           // stats per plane (T + 6 rows + 6 cols + 4x 3x3 corners)
#define PRE_BLK 128        // prelude blocks (co-resident guaranteed)

// Scratch (static device memory -- allocation-free)
__device__ float g_buf[(size_t)NPLANE * HWSZ];     // ping-pong x buffer
__device__ float g_st[2][NSLOT * NPLANE];          // plane stats, ping-pong by layer
__device__ float g_scaleArr[NLAYERS * NPLANE];     // per-layer per-plane scale
__device__ float g_H[NPLANE], g_C[NPLANE];         // LSTM state
__device__ float g_GI[BB * 3 * CC];                // input-path gates
__device__ float g_GH2[3 * CC];                    // 2nd-cell hidden gates (row 0)
__device__ int   g_bar[8], g_dep[8];               // prelude barriers (self-resetting)

__device__ __forceinline__ float sigmf(float x) { return 1.0f / (1.0f + __expf(-x)); }
__device__ __forceinline__ float tanhfast(float x) {
    float e = __expf(2.0f * x);
    return __fdividef(e - 1.0f, e + 1.0f);
}

// stat slot maps (rings 0..2 on each side)
__device__ __forceinline__ int rslot(int r) { return (r < 3) ? 1 + r : 4 + (r - 25); }
__device__ __forceinline__ int cslot(int c) { return (c < 3) ? 7 + c : 10 + (c - 25); }
__device__ __forceinline__ int pslot(int i, int j) {
    int bi = (i < 3) ? 0 : 1, ii = (i < 3) ? i : i - 25;
    int bj = (j < 3) ? 0 : 1, jj = (j < 3) ? j : j - 25;
    return 13 + (bi * 2 + bj) * 9 + ii * 3 + jj;
}

// ---------------- pool: warp-per-plane, lane = column; emits 49 stats ----------------
__global__ void __launch_bounds__(256) k_pool(const float* __restrict__ x) {
    int tid = threadIdx.x, lane = tid & 31, w = tid >> 5;
    int plane = blockIdx.x * PPB + w;
    const float* p = x + (size_t)plane * HWSZ;
    float* st = g_st[0];
    float cs = 0.f;
    #pragma unroll
    for (int y = 0; y < HH; y++) {
        float v = (lane < WW) ? p[y * WW + lane] : 0.f;
        cs += v;
        if (y < 3 || y > 24) {
            float rs = v;
            #pragma unroll
            for (int o = 16; o; o >>= 1) rs += __shfl_down_sync(0xffffffffu, rs, o);
            if (lane == 0) st[rslot(y) * NPLANE + plane] = rs;
            if (lane < 3 || (lane > 24 && lane < WW)) st[pslot(y, lane) * NPLANE + plane] = v;
        }
    }
    if (lane < 3 || (lane > 24 && lane < WW)) st[cslot(lane) * NPLANE + plane] = cs;
    float T = cs;
    #pragma unroll
    for (int o = 16; o; o >>= 1) T += __shfl_down_sync(0xffffffffu, T, o);
    if (lane == 0) st[plane] = T;    // slot 0
}

// ---------------- analytic stat propagation: x' = s*x + conv3x3(x) ----------------
__device__ void propagate(const float* __restrict__ stIn, float* __restrict__ stOut,
                          int plane, float s, const float* wq, int RIN) {
    // T'
    float T = __ldcg(&stIn[plane]);
    float sc = 0.f;
    #pragma unroll
    for (int dy = -1; dy <= 1; dy++)
    #pragma unroll
    for (int dx = -1; dx <= 1; dx++) {
        float S = T;
        if (dy) S -= __ldcg(&stIn[rslot(dy < 0 ? 27 : 0) * NPLANE + plane]);
        if (dx) S -= __ldcg(&stIn[cslot(dx < 0 ? 27 : 0) * NPLANE + plane]);
        if (dy && dx) S += __ldcg(&stIn[pslot(dy < 0 ? 27 : 0, dx < 0 ? 27 : 0) * NPLANE + plane]);
        sc += wq[(dy + 1) * 3 + (dx + 1)] * S;
    }
    stOut[plane] = s * T + sc;

    int ROUT = RIN - 1;
    // rows
    for (int ii = 0; ii < ROUT; ii++)
    for (int side = 0; side < 2; side++) {
        int i = side ? 27 - ii : ii;
        float acc = s * __ldcg(&stIn[rslot(i) * NPLANE + plane]);
        for (int dy = -1; dy <= 1; dy++) {
            int r = i + dy; if (r < 0 || r > 27) continue;
            float rv  = __ldcg(&stIn[rslot(r) * NPLANE + plane]);
            float p0  = __ldcg(&stIn[pslot(r, 0) * NPLANE + plane]);
            float p27 = __ldcg(&stIn[pslot(r, 27) * NPLANE + plane]);
            acc += wq[(dy + 1) * 3 + 0] * (rv - p27);   // dx=-1 loses col 27
            acc += wq[(dy + 1) * 3 + 1] * rv;
            acc += wq[(dy + 1) * 3 + 2] * (rv - p0);    // dx=+1 loses col 0
        }
        stOut[rslot(i) * NPLANE + plane] = acc;
    }
    // cols
    for (int jj = 0; jj < ROUT; jj++)
    for (int side = 0; side < 2; side++) {
        int j = side ? 27 - jj : jj;
        float acc = s * __ldcg(&stIn[cslot(j) * NPLANE + plane]);
        for (int dx = -1; dx <= 1; dx++) {
            int cc = j + dx; if (cc < 0 || cc > 27) continue;
            float cv = __ldcg(&stIn[cslot(cc) * NPLANE + plane]);
            float pt = __ldcg(&stIn[pslot(0, cc) * NPLANE + plane]);
            float pb = __ldcg(&stIn[pslot(27, cc) * NPLANE + plane]);
            acc += wq[0 * 3 + (dx + 1)] * (cv - pb);    // dy=-1 loses row 27
            acc += wq[1 * 3 + (dx + 1)] * cv;
            acc += wq[2 * 3 + (dx + 1)] * (cv - pt);    // dy=+1 loses row 0
        }
        stOut[cslot(j) * NPLANE + plane] = acc;
    }
    // corner pixels
    for (int ii = 0; ii < ROUT; ii++)
    for (int si = 0; si < 2; si++) {
        int i = si ? 27 - ii : ii;
        for (int jj = 0; jj < ROUT; jj++)
        for (int sj = 0; sj < 2; sj++) {
            int j = sj ? 27 - jj : jj;
            float acc = s * __ldcg(&stIn[pslot(i, j) * NPLANE + plane]);
            for (int dy = -1; dy <= 1; dy++)
            for (int dx = -1; dx <= 1; dx++) {
                int r = i + dy, cc = j + dx;
                if (r < 0 || r > 27 || cc < 0 || cc > 27) continue;
                acc += wq[(dy + 1) * 3 + (dx + 1)] * __ldcg(&stIn[pslot(r, cc) * NPLANE + plane]);
            }
            stOut[pslot(i, j) * NPLANE + plane] = acc;
        }
    }
}

__device__ __forceinline__ void dbar(int i) {
    __threadfence();
    __syncthreads();
    if (threadIdx.x == 0) {
        atomicAdd(&g_bar[i], 1);
        while (atomicAdd(&g_bar[i], 0) < PRE_BLK) __nanosleep(64);
        int d = atomicAdd(&g_dep[i], 1);
        if (d == PRE_BLK - 1) { atomicExch(&g_bar[i], 0); atomicExch(&g_dep[i], 0); }
    }
    __syncthreads();
}

// ---------------- prelude: all 4 layers of cell + scale + stat propagation ----------------
__global__ void __launch_bounds__(256) k_prelude(
        const float* __restrict__ w_ih_l1, const float* __restrict__ b_ih_l1,
        const float* __restrict__ w_ih_l2, const float* __restrict__ b_ih_l2,
        const float* __restrict__ w_hh_l1, const float* __restrict__ b_hh_l1,
        const float* __restrict__ w_hh_l2, const float* __restrict__ b_hh_l2,
        const float* __restrict__ dw) {
    __shared__ __align__(16) float sin0[CC], sin1[CC], snh[CC];
    __shared__ __align__(16) float shid[64];
    __shared__ __align__(16) float sh2[HID];
    int tid = threadIdx.x, lane = tid & 31, w = tid >> 5;  // 8 warps

    for (int l = 0; l < NLAYERS; l++) {
        const float* stIn = g_st[l & 1];
        float* stOut = g_st[(l + 1) & 1];

        // ---- phase A: cells (blocks 0..63, one batch each) ----
        if (blockIdx.x < BB) {
            int b = blockIdx.x;
            if (tid < 128) {
                float4 tv;
                tv.x = __ldcg(&stIn[b * CC + tid * 4 + 0]);
                tv.y = __ldcg(&stIn[b * CC + tid * 4 + 1]);
                tv.z = __ldcg(&stIn[b * CC + tid * 4 + 2]);
                tv.w = __ldcg(&stIn[b * CC + tid * 4 + 3]);
                float inv = 1.0f / HWSZ;
                ((float4*)sin0)[tid] = make_float4(tv.x * inv, tv.y * inv, tv.z * inv, tv.w * inv);
            } else {
                int t2 = tid - 128;
                float4 hv = make_float4(0.f, 0.f, 0.f, 0.f);
                if (l > 0) {
                    hv.x = __ldcg(&g_H[b * CC + t2 * 4 + 0]);
                    hv.y = __ldcg(&g_H[b * CC + t2 * 4 + 1]);
                    hv.z = __ldcg(&g_H[b * CC + t2 * 4 + 2]);
                    hv.w = __ldcg(&g_H[b * CC + t2 * 4 + 3]);
                }
                ((float4*)sin1)[t2] = hv;
            }
            __syncthreads();
            // both bottleneck GEMVs: 64 dots of 512
            #pragma unroll
            for (int t = 0; t < 8; t++) {
                int d = t * 8 + w;
                int path = d >> 5, k = d & 31;
                const float4* wr4 = (const float4*)((path ? w_hh_l1 : w_ih_l1) + k * CC);
                const float4* in4 = (const float4*)(path ? sin1 : sin0);
                float s = 0.f;
                #pragma unroll
                for (int j = lane; j < 128; j += 32) {
                    float4 wv = wr4[j], iv = in4[j];
                    s += iv.x * wv.x + iv.y * wv.y + iv.z * wv.z + iv.w * wv.w;
                }
                #pragma unroll
                for (int o = 16; o; o >>= 1) s += __shfl_down_sync(0xffffffffu, s, o);
                if (lane == 0) shid[d] = fmaxf(s + (path ? b_hh_l1 : b_ih_l1)[k], 0.f);
            }
            __syncthreads();
            // phase-2 gates: 2 channels per thread
            #pragma unroll
            for (int half = 0; half < 2; half++) {
                int c = tid + half * 256;
                float gi[3], gh[3];
                #pragma unroll
                for (int g = 0; g < 3; g++) {
                    gi[g] = b_ih_l2[g * CC + c];
                    gh[g] = b_hh_l2[g * CC + c];
                }
                #pragma unroll
                for (int g = 0; g < 3; g++) {
                    const float4* wi4 = (const float4*)&w_ih_l2[(g * CC + c) * HID];
                    const float4* wh4 = (const float4*)&w_hh_l2[(g * CC + c) * HID];
                    #pragma unroll
                    for (int q = 0; q < 8; q++) {
                        float4 wi = wi4[q], wh = wh4[q];
                        int k = q * 4;
                        gi[g] += shid[k]*wi.x + shid[k+1]*wi.y + shid[k+2]*wi.z + shid[k+3]*wi.w;
                        gh[g] += shid[32+k]*wh.x + shid[32+k+1]*wh.y + shid[32+k+2]*wh.z + shid[32+k+3]*wh.w;
                    }
                    g_GI[(b * 3 + g) * CC + c] = gi[g];
                }
                float cx = (l == 0) ? 0.f : __ldcg(&g_C[b * CC + c]);
                float ig = sigmf(gi[0] + gh[0]);
                float fg = sigmf(gi[1] + gh[1]);
                float cg = tanhfast(gi[2] + gh[2]);
                float nc = fg * cx + ig * cg;
                float nh = sigmf(nc);
                g_C[b * CC + c] = nc;
                g_H[b * CC + c] = nh;
                snh[c] = nh;
            }
            // block-0 tail: gh2 from fresh ht[0]
            if (b == 0) {
                __syncthreads();
                #pragma unroll
                for (int t = 0; t < 4; t++) {
                    int k = t * 8 + w;
                    const float4* wr4 = (const float4*)(w_hh_l1 + k * CC);
                    float s = 0.f;
                    #pragma unroll
                    for (int j = lane; j < 128; j += 32) {
                        float4 wv = wr4[j], iv = ((const float4*)snh)[j];
                        s += iv.x * wv.x + iv.y * wv.y + iv.z * wv.z + iv.w * wv.w;
                    }
                    #pragma unroll
                    for (int o = 16; o; o >>= 1) s += __shfl_down_sync(0xffffffffu, s, o);
                    if (lane == 0) sh2[k] = fmaxf(s + b_hh_l1[k], 0.f);
                }
                __syncthreads();
                #pragma unroll
                for (int j = tid; j < 3 * CC; j += 256) {
                    float acc = b_hh_l2[j];
                    const float4* wh4 = (const float4*)&w_hh_l2[j * HID];
                    #pragma unroll
                    for (int q = 0; q < 8; q++) {
                        float4 wh = wh4[q];
                        int k = q * 4;
                        acc += sh2[k]*wh.x + sh2[k+1]*wh.y + sh2[k+2]*wh.z + sh2[k+3]*wh.w;
                    }
                    g_GH2[j] = acc;
                }
            }
        }
        dbar(2 * l);

        // ---- phase B: scale + stat propagation (all 128 blocks, 1 thread/plane) ----
        {
            int plane = blockIdx.x * 256 + tid;
            int b = plane >> 9, c = plane & 511;
            float i2 = __ldcg(&g_GI[(b * 3 + 0) * CC + c]) + __ldcg(&g_GH2[c]);
            float f2 = __ldcg(&g_GI[(b * 3 + 1) * CC + c]) + __ldcg(&g_GH2[CC + c]);
            float c2 = __ldcg(&g_GI[(b * 3 + 2) * CC + c]) + __ldcg(&g_GH2[2 * CC + c]);
            float ct0 = __ldcg(&g_C[c]);
            float s = 1.0f + sigmf(sigmf(f2) * ct0 + sigmf(i2) * tanhfast(c2));
            g_scaleArr[l * NPLANE + plane] = s;
            if (l < NLAYERS - 1) {
                float wq[9];
                const float* wp = dw + c * 9;
                #pragma unroll
                for (int q = 0; q < 9; q++) wq[q] = wp[q];
                propagate(stIn, stOut, plane, s, wq, 3 - l);
            }
        }
        if (l < NLAYERS - 1) dbar(2 * l + 1);
    }
}

// ---------------- update: warp-per-plane rolling stencil (pure stream) ----------------
__global__ void __launch_bounds__(256) k_update(
        const float* __restrict__ xin, float* __restrict__ xout,
        const float* __restrict__ dw, int l) {
    __shared__ __align__(16) float s[PPB * HWSZ + 4];
    int lane = threadIdx.x & 31, w = threadIdx.x >> 5;
    int plane = blockIdx.x * PPB + w;
    int c = plane & 511;
    float* sp = s + w * HWSZ;

    const float4* in4 = (const float4*)(xin + (size_t)plane * HWSZ);
    float4* sp4 = (float4*)sp;
    #pragma unroll
    for (int q = lane; q < QPP; q += 32) sp4[q] = in4[q];

    float scale = g_scaleArr[l * NPLANE + plane];
    float wq[9];
    const float* wp = dw + c * 9;
    #pragma unroll
    for (int q = 0; q < 9; q++) wq[q] = wp[q];
    __syncwarp();

    int x = lane;
    bool active = x < WW;
    int xi = active ? x : 0;
    bool notL = (x > 0), notR = (x < WW - 1);

    float aL = 0, aC = 0, aR = 0, bL, bC, bR, cL, cC, cR;
    bC = sp[xi];
    bL = __shfl_up_sync(0xffffffffu, bC, 1);   if (!notL) bL = 0;
    bR = __shfl_down_sync(0xffffffffu, bC, 1); if (!notR) bR = 0;
    cC = sp[WW + xi];
    cL = __shfl_up_sync(0xffffffffu, cC, 1);   if (!notL) cL = 0;
    cR = __shfl_down_sync(0xffffffffu, cC, 1); if (!notR) cR = 0;

    float* outp = xout + (size_t)plane * HWSZ;
    #pragma unroll
    for (int y = 0; y < HH; y++) {
        float conv = wq[0] * aL + wq[1] * aC + wq[2] * aR
                   + wq[3] * bL + wq[4] * bC + wq[5] * bR
                   + wq[6] * cL + wq[7] * cC + wq[8] * cR;
        float o = fmaf(bC, scale, conv);
        if (active) outp[y * WW + x] = o;
        aL = bL; aC = bC; aR = bR;
        bL = cL; bC = cC; bR = cR;
        if (y + 2 < HH) {
            cC = sp[(y + 2) * WW + xi];
            cL = __shfl_up_sync(0xffffffffu, cC, 1);   if (!notL) cL = 0;
            cR = __shfl_down_sync(0xffffffffu, cC, 1); if (!notR) cR = 0;
        } else { cC = cL = cR = 0.f; }
    }
}

extern "C" void kernel_launch(void* const* d_in, const int* in_sizes, int n_in,
                              void* d_out, int out_size) {
    const float* x        = (const float*)d_in[0];
    const float* w_ih_l1  = (const float*)d_in[1];
    const float* b_ih_l1  = (const float*)d_in[2];
    const float* w_ih_l2  = (const float*)d_in[3];
    const float* b_ih_l2  = (const float*)d_in[4];
    const float* w_hh_l1  = (const float*)d_in[5];
    const float* b_hh_l1  = (const float*)d_in[6];
    const float* w_hh_l2  = (const float*)d_in[7];
    const float* b_hh_l2  = (const float*)d_in[8];
    const float* dw       = (const float*)d_in[9];
    float* out = (float*)d_out;

    float* buf = nullptr;
    cudaGetSymbolAddress((void**)&buf, g_buf);

    k_pool<<<NUP, 256>>>(x);
    k_prelude<<<PRE_BLK, 256>>>(w_ih_l1, b_ih_l1, w_ih_l2, b_ih_l2,
                                w_hh_l1, b_hh_l1, w_hh_l2, b_hh_l2, dw);

    const float* cur = x;
    for (int l = 0; l < NLAYERS; l++) {
        float* nxt = ((l & 1) == 0) ? buf : out;   // l0->buf, l1->out, l2->buf, l3->out
        k_update<<<NUP, 256>>>(cur, nxt, dw, l);
        cur = nxt;
    }
}

// round 14
// speedup vs baseline: 1.3899x; 1.3899x over previous
#include <cuda_runtime.h>

#define BB 64
#define CC 512
#define HH 28
#define WW 28
#define HWSZ (HH*WW)
#define HID 32
#define NPLANE (BB*CC)
#define NLAYERS 4
#define QPP 196            // float4 quads per plane
#define PPB 8              // planes per block (1 warp each)
#define NUP (NPLANE/PPB)   // 4096 update blocks
#define NSLOT 49           // stats per plane

// Scratch (static device memory -- allocation-free)
__device__ float g_st4[4][NSLOT * NPLANE];       // per-layer plane stats (no aliasing)
__device__ float g_scaleArr[NLAYERS * NPLANE];   // all scales, computed upfront

__device__ __forceinline__ float sigmf(float x) { return 1.0f / (1.0f + __expf(-x)); }
__device__ __forceinline__ float tanhfast(float x) {
    float e = __expf(2.0f * x);
    return __fdividef(e - 1.0f, e + 1.0f);
}

// stat slot maps (rings 0..2 on each side)
__device__ __forceinline__ int rslot(int r) { return (r < 3) ? 1 + r : 4 + (r - 25); }
__device__ __forceinline__ int cslot(int c) { return (c < 3) ? 7 + c : 10 + (c - 25); }
__device__ __forceinline__ int pslot(int i, int j) {
    int bi = (i < 3) ? 0 : 1, ii = (i < 3) ? i : i - 25;
    int bj = (j < 3) ? 0 : 1, jj = (j < 3) ? j : j - 25;
    return 13 + (bi * 2 + bj) * 9 + ii * 3 + jj;
}

// ---------------- pool: warp-per-plane; emits 49 stats (verified R13) ----------------
__global__ void __launch_bounds__(256) k_pool(const float* __restrict__ x) {
    int tid = threadIdx.x, lane = tid & 31, w = tid >> 5;
    int plane = blockIdx.x * PPB + w;
    const float* p = x + (size_t)plane * HWSZ;
    float* st = g_st4[0];
    float cs = 0.f;
    #pragma unroll
    for (int y = 0; y < HH; y++) {
        float v = (lane < WW) ? p[y * WW + lane] : 0.f;
        cs += v;
        if (y < 3 || y > 24) {
            float rs = v;
            #pragma unroll
            for (int o = 16; o; o >>= 1) rs += __shfl_down_sync(0xffffffffu, rs, o);
            if (lane == 0) st[rslot(y) * NPLANE + plane] = rs;
            if (lane < 3 || (lane > 24 && lane < WW)) st[pslot(y, lane) * NPLANE + plane] = v;
        }
    }
    if (lane < 3 || (lane > 24 && lane < WW)) st[cslot(lane) * NPLANE + plane] = cs;
    float T = cs;
    #pragma unroll
    for (int o = 16; o; o >>= 1) T += __shfl_down_sync(0xffffffffu, T, o);
    if (lane == 0) st[plane] = T;    // slot 0
}

// ---------------- analytic stat propagation (templated, fully unrolled) ----------------
template<int ROUT>
__device__ __forceinline__ void propagate(const float* __restrict__ stIn,
                                          float* __restrict__ stOut,
                                          int plane, float s, const float* wq) {
    float T = stIn[plane];
    float sc = 0.f;
    #pragma unroll
    for (int dy = -1; dy <= 1; dy++)
    #pragma unroll
    for (int dx = -1; dx <= 1; dx++) {
        float S = T;
        if (dy) S -= stIn[rslot(dy < 0 ? 27 : 0) * NPLANE + plane];
        if (dx) S -= stIn[cslot(dx < 0 ? 27 : 0) * NPLANE + plane];
        if (dy && dx) S += stIn[pslot(dy < 0 ? 27 : 0, dx < 0 ? 27 : 0) * NPLANE + plane];
        sc += wq[(dy + 1) * 3 + (dx + 1)] * S;
    }
    stOut[plane] = s * T + sc;

    #pragma unroll
    for (int ii = 0; ii < ROUT; ii++)
    #pragma unroll
    for (int side = 0; side < 2; side++) {
        int i = side ? 27 - ii : ii;
        float acc = s * stIn[rslot(i) * NPLANE + plane];
        #pragma unroll
        for (int dy = -1; dy <= 1; dy++) {
            int r = i + dy; if (r < 0 || r > 27) continue;
            float rv  = stIn[rslot(r) * NPLANE + plane];
            float p0  = stIn[pslot(r, 0) * NPLANE + plane];
            float p27 = stIn[pslot(r, 27) * NPLANE + plane];
            acc += wq[(dy + 1) * 3 + 0] * (rv - p27);
            acc += wq[(dy + 1) * 3 + 1] * rv;
            acc += wq[(dy + 1) * 3 + 2] * (rv - p0);
        }
        stOut[rslot(i) * NPLANE + plane] = acc;
    }
    #pragma unroll
    for (int jj = 0; jj < ROUT; jj++)
    #pragma unroll
    for (int side = 0; side < 2; side++) {
        int j = side ? 27 - jj : jj;
        float acc = s * stIn[cslot(j) * NPLANE + plane];
        #pragma unroll
        for (int dx = -1; dx <= 1; dx++) {
            int cc = j + dx; if (cc < 0 || cc > 27) continue;
            float cv = stIn[cslot(cc) * NPLANE + plane];
            float pt = stIn[pslot(0, cc) * NPLANE + plane];
            float pb = stIn[pslot(27, cc) * NPLANE + plane];
            acc += wq[0 * 3 + (dx + 1)] * (cv - pb);
            acc += wq[1 * 3 + (dx + 1)] * cv;
            acc += wq[2 * 3 + (dx + 1)] * (cv - pt);
        }
        stOut[cslot(j) * NPLANE + plane] = acc;
    }
    #pragma unroll
    for (int ii = 0; ii < ROUT; ii++)
    #pragma unroll
    for (int si = 0; si < 2; si++) {
        int i = si ? 27 - ii : ii;
        #pragma unroll
        for (int jj = 0; jj < ROUT; jj++)
        #pragma unroll
        for (int sj = 0; sj < 2; sj++) {
            int j = sj ? 27 - jj : jj;
            float acc = s * stIn[pslot(i, j) * NPLANE + plane];
            #pragma unroll
            for (int dy = -1; dy <= 1; dy++)
            #pragma unroll
            for (int dx = -1; dx <= 1; dx++) {
                int r = i + dy, cc = j + dx;
                if (r < 0 || r > 27 || cc < 0 || cc > 27) continue;
                acc += wq[(dy + 1) * 3 + (dx + 1)] * stIn[pslot(r, cc) * NPLANE + plane];
            }
            stOut[pslot(i, j) * NPLANE + plane] = acc;
        }
    }
}

// ---------------- prelude: 64 independent blocks, no inter-block sync ----------------
// Block b computes, per layer: cell for batch b AND (redundantly) batch 0,
// gh2 from fresh ht[0], scales for its 512(+512) planes, and stat propagation.
__global__ void __launch_bounds__(512) k_prelude(
        const float* __restrict__ w_ih_l1, const float* __restrict__ b_ih_l1,
        const float* __restrict__ w_ih_l2, const float* __restrict__ b_ih_l2,
        const float* __restrict__ w_hh_l1, const float* __restrict__ b_hh_l1,
        const float* __restrict__ w_hh_l2, const float* __restrict__ b_hh_l2,
        const float* __restrict__ dw) {
    __shared__ __align__(16) float sseqB[CC], sseq0[CC], shtB[CC], sht0[CC];
    __shared__ __align__(16) float hidB[64], hid0[64], hid2[HID];
    int b = blockIdx.x, tid = threadIdx.x, lane = tid & 31, w = tid >> 5;  // 16 warps
    int c = tid;
    float ctB = 0.f, ct0r = 0.f;
    shtB[tid] = 0.f; sht0[tid] = 0.f;
    float wq[9];
    #pragma unroll
    for (int q = 0; q < 9; q++) wq[q] = dw[c * 9 + q];
    __syncthreads();

    for (int l = 0; l < NLAYERS; l++) {
        const float* stIn = g_st4[l];
        float* stOut = g_st4[(l < 3) ? l + 1 : 3];
        // seq inputs from stats (thread-own values from own propagate last layer)
        sseqB[tid] = stIn[b * CC + tid] * (1.0f / HWSZ);
        if (b) sseq0[tid] = stIn[tid] * (1.0f / HWSZ);
        __syncthreads();

        // 128 dots of 512: warps 0-7 batch b, warps 8-15 batch 0 (skip if b==0)
        {
            int isB0 = (w >= 8);
            if (!isB0 || b != 0) {
                const float* inI = isB0 ? sseq0 : sseqB;
                const float* inH = isB0 ? sht0 : shtB;
                float* outH = isB0 ? hid0 : hidB;
                int w8 = w & 7;
                #pragma unroll
                for (int t = 0; t < 8; t++) {
                    int d = w8 * 8 + t;
                    int path = d >> 5, k = d & 31;
                    const float4* wr4 = (const float4*)((path ? w_hh_l1 : w_ih_l1) + k * CC);
                    const float4* in4 = (const float4*)(path ? inH : inI);
                    float s = 0.f;
                    #pragma unroll
                    for (int j = lane; j < 128; j += 32) {
                        float4 wv = wr4[j], iv = in4[j];
                        s += iv.x * wv.x + iv.y * wv.y + iv.z * wv.z + iv.w * wv.w;
                    }
                    #pragma unroll
                    for (int o = 16; o; o >>= 1) s += __shfl_down_sync(0xffffffffu, s, o);
                    if (lane == 0) outH[d] = fmaxf(s + (path ? b_hh_l1 : b_ih_l1)[k], 0.f);
                }
            }
        }
        __syncthreads();
        const float* h0 = (b == 0) ? hidB : hid0;

        // phase 2 gates for both batches, channel c = tid; shared weight loads
        float giB[3], gi0[3], ghB[3], gh0[3];
        #pragma unroll
        for (int g = 0; g < 3; g++) {
            float bi2 = b_ih_l2[g * CC + c], bh2 = b_hh_l2[g * CC + c];
            const float4* wi4 = (const float4*)&w_ih_l2[(g * CC + c) * HID];
            const float4* wh4 = (const float4*)&w_hh_l2[(g * CC + c) * HID];
            float sB = 0.f, s0 = 0.f, tB = 0.f, t0 = 0.f;
            #pragma unroll
            for (int q = 0; q < 8; q++) {
                float4 wi = wi4[q], wh = wh4[q];
                int k = q * 4;
                sB += hidB[k]*wi.x + hidB[k+1]*wi.y + hidB[k+2]*wi.z + hidB[k+3]*wi.w;
                s0 += h0[k]*wi.x + h0[k+1]*wi.y + h0[k+2]*wi.z + h0[k+3]*wi.w;
                tB += hidB[32+k]*wh.x + hidB[32+k+1]*wh.y + hidB[32+k+2]*wh.z + hidB[32+k+3]*wh.w;
                t0 += h0[32+k]*wh.x + h0[32+k+1]*wh.y + h0[32+k+2]*wh.z + h0[32+k+3]*wh.w;
            }
            giB[g] = sB + bi2; gi0[g] = s0 + bi2;
            ghB[g] = tB + bh2; gh0[g] = t0 + bh2;
        }
        {
            float ig = sigmf(giB[0] + ghB[0]);
            float fg = sigmf(giB[1] + ghB[1]);
            float cg = tanhfast(giB[2] + ghB[2]);
            ctB = fg * ctB + ig * cg;
            shtB[c] = sigmf(ctB);
        }
        {
            float ig = sigmf(gi0[0] + gh0[0]);
            float fg = sigmf(gi0[1] + gh0[1]);
            float cg = tanhfast(gi0[2] + gh0[2]);
            ct0r = fg * ct0r + ig * cg;
            sht0[c] = sigmf(ct0r);
        }
        __syncthreads();

        // hid2 = relu(W1h ht[0] + b1h): 32 dots, 2 per warp
        #pragma unroll
        for (int t = 0; t < 2; t++) {
            int k = w * 2 + t;
            const float4* wr4 = (const float4*)(w_hh_l1 + k * CC);
            float s = 0.f;
            #pragma unroll
            for (int j = lane; j < 128; j += 32) {
                float4 wv = wr4[j], iv = ((const float4*)sht0)[j];
                s += iv.x * wv.x + iv.y * wv.y + iv.z * wv.z + iv.w * wv.w;
            }
            #pragma unroll
            for (int o = 16; o; o >>= 1) s += __shfl_down_sync(0xffffffffu, s, o);
            if (lane == 0) hid2[k] = fmaxf(s + b_hh_l1[k], 0.f);
        }
        __syncthreads();

        // gh2 for own channel (3 values, in registers)
        float gh2r[3];
        #pragma unroll
        for (int g = 0; g < 3; g++) {
            float acc = b_hh_l2[g * CC + c];
            const float4* wh4 = (const float4*)&w_hh_l2[(g * CC + c) * HID];
            #pragma unroll
            for (int q = 0; q < 8; q++) {
                float4 wh = wh4[q];
                int k = q * 4;
                acc += hid2[k]*wh.x + hid2[k+1]*wh.y + hid2[k+2]*wh.z + hid2[k+3]*wh.w;
            }
            gh2r[g] = acc;
        }

        // scales
        float i2 = giB[0] + gh2r[0], f2 = giB[1] + gh2r[1], c2 = giB[2] + gh2r[2];
        float sB = 1.0f + sigmf(sigmf(f2) * ct0r + sigmf(i2) * tanhfast(c2));
        g_scaleArr[l * NPLANE + b * CC + c] = sB;
        float s0v = sB;
        if (b) {
            float i0 = gi0[0] + gh2r[0], f0 = gi0[1] + gh2r[1], c0 = gi0[2] + gh2r[2];
            s0v = 1.0f + sigmf(sigmf(f0) * ct0r + sigmf(i0) * tanhfast(c0));
            g_scaleArr[l * NPLANE + c] = s0v;   // identical across blocks: benign
        }

        // analytic stat propagation for own planes (+ batch 0 redundantly)
        if (l == 0) {
            propagate<2>(stIn, stOut, b * CC + c, sB, wq);
            if (b) propagate<2>(stIn, stOut, c, s0v, wq);
        } else if (l == 1) {
            propagate<1>(stIn, stOut, b * CC + c, sB, wq);
            if (b) propagate<1>(stIn, stOut, c, s0v, wq);
        } else if (l == 2) {
            propagate<0>(stIn, stOut, b * CC + c, sB, wq);
            if (b) propagate<0>(stIn, stOut, c, s0v, wq);
        }
        __syncthreads();
    }
}

// ---------------- fused 4-pass update: warp-per-plane, all passes in registers ----------------
__global__ void __launch_bounds__(256) k_update4(
        const float* __restrict__ xin, float* __restrict__ xout,
        const float* __restrict__ dw) {
    __shared__ __align__(16) float smem[PPB * HWSZ + 32];
    int lane = threadIdx.x & 31, w = threadIdx.x >> 5;
    int plane = blockIdx.x * PPB + w;
    int c = plane & 511;
    float* sp = smem + w * HWSZ;

    const float4* in4 = (const float4*)(xin + (size_t)plane * HWSZ);
    float4* sp4 = (float4*)sp;
    #pragma unroll
    for (int q = lane; q < QPP; q += 32) sp4[q] = in4[q];

    float wq[9];
    #pragma unroll
    for (int q = 0; q < 9; q++) wq[q] = dw[c * 9 + q];
    float sc[NLAYERS];
    #pragma unroll
    for (int p = 0; p < NLAYERS; p++) sc[p] = g_scaleArr[p * NPLANE + plane];
    __syncwarp();

    int x = lane;
    bool active = x < WW;
    int xi = active ? x : (WW - 1);
    bool notL = (x > 0), notR = (x < WW - 1);

    float col[HH];
    #pragma unroll
    for (int y = 0; y < HH; y++) col[y] = sp[y * WW + xi];

    #pragma unroll
    for (int p = 0; p < NLAYERS; p++) {
        float s = sc[p];
        float aL = 0.f, aC = 0.f, aR = 0.f;
        float bC = col[0];
        float bL = __shfl_up_sync(0xffffffffu, bC, 1);   if (!notL) bL = 0.f;
        float bR = __shfl_down_sync(0xffffffffu, bC, 1); if (!notR) bR = 0.f;
        float cC = col[1];
        float cL = __shfl_up_sync(0xffffffffu, cC, 1);   if (!notL) cL = 0.f;
        float cR = __shfl_down_sync(0xffffffffu, cC, 1); if (!notR) cR = 0.f;
        #pragma unroll
        for (int y = 0; y < HH; y++) {
            float conv = wq[0] * aL + wq[1] * aC + wq[2] * aR
                       + wq[3] * bL + wq[4] * bC + wq[5] * bR
                       + wq[6] * cL + wq[7] * cC + wq[8] * cR;
            float o = fmaf(bC, s, conv);
            aL = bL; aC = bC; aR = bR;
            bL = cL; bC = cC; bR = cR;
            col[y] = o;                         // row y no longer needed
            if (y + 2 < HH) {
                cC = col[y + 2];                // still original for this pass
                cL = __shfl_up_sync(0xffffffffu, cC, 1);   if (!notL) cL = 0.f;
                cR = __shfl_down_sync(0xffffffffu, cC, 1); if (!notR) cR = 0.f;
            } else { cC = cL = cR = 0.f; }
        }
    }

    // write back via smem for coalesced stores
    #pragma unroll
    for (int y = 0; y < HH; y++) if (active) sp[y * WW + x] = col[y];
    __syncwarp();
    float4* out4 = (float4*)(xout + (size_t)plane * HWSZ);
    #pragma unroll
    for (int q = lane; q < QPP; q += 32) out4[q] = sp4[q];
}

extern "C" void kernel_launch(void* const* d_in, const int* in_sizes, int n_in,
                              void* d_out, int out_size) {
    const float* x        = (const float*)d_in[0];
    const float* w_ih_l1  = (const float*)d_in[1];
    const float* b_ih_l1  = (const float*)d_in[2];
    const float* w_ih_l2  = (const float*)d_in[3];
    const float* b_ih_l2  = (const float*)d_in[4];
    const float* w_hh_l1  = (const float*)d_in[5];
    const float* b_hh_l1  = (const float*)d_in[6];
    const float* w_hh_l2  = (const float*)d_in[7];
    const float* b_hh_l2  = (const float*)d_in[8];
    const float* dw       = (const float*)d_in[9];
    float* out = (float*)d_out;

    k_pool<<<NUP, 256>>>(x);
    k_prelude<<<BB, 512>>>(w_ih_l1, b_ih_l1, w_ih_l2, b_ih_l2,
                           w_hh_l1, b_hh_l1, w_hh_l2, b_hh_l2, dw);
    k_update4<<<NUP, 256>>>(x, out, dw);
}